// round 8
// baseline (speedup 1.0000x reference)
#include <cuda_runtime.h>
#include <math.h>
#include <float.h>

#define NN    512
#define FIN   256
#define HF    64
#define NC    64
#define TOPK  12
#define LALPHA 0.2f
#define MAXE  32
#define MAXR  16   // max distinct rows/cols (math guarantees <= 11)
#define CAND_CAP 8192

// ---------------- scratch (device globals; zero-initialized) ----------------
__device__ float    g_A[NN * NN];
__device__ int      g_nc2;                 // candidate count (reset by k_head)
__device__ unsigned g_cand2[CAND_CAP];
__device__ int      g_ne_raw;              // edge count (reset by k_final)
__device__ int      g_ei_raw[MAXE], g_ej_raw[MAXE];
__device__ float    g_w1[NN * FIN];
__device__ float    g_w2[NN * FIN];
__device__ float    g_WhN[(size_t)NN * MAXR * HF];   // [h][colidx][k]
__device__ float    g_E2T[NN * NN];                  // [h][j]
__device__ float    g_WhOut[MAXR * NC];              // zeroed by k_adj blk0

__device__ __forceinline__ float lrelu(float x) { return x >= 0.f ? x : LALPHA * x; }
__device__ __forceinline__ float elu1(float x)  { return x > 0.f ? x : expm1f(x); }
__device__ __forceinline__ unsigned fkey(float f) {
    unsigned u = __float_as_uint(f);
    return (u & 0x80000000u) ? ~u : (u | 0x80000000u);
}

// one-thread prep: sort raw edges, dedup rows/cols (deterministic)
__device__ __forceinline__ void prep0(int* ne_o, int* nr_o, int* nc_o,
                                      int* Ei, int* Ej, int* Er, int* Ec,
                                      int* Rows, int* Cols) {
    int ne = g_ne_raw; if (ne > MAXE) ne = MAXE;
    int ei[MAXE], ej[MAXE];
    for (int e = 0; e < ne; e++) { ei[e] = g_ei_raw[e]; ej[e] = g_ej_raw[e]; }
    for (int a = 1; a < ne; a++) {
        int ki = ei[a], kj = ej[a]; int key = ki * NN + kj; int b = a - 1;
        while (b >= 0 && ei[b] * NN + ej[b] > key) { ei[b+1] = ei[b]; ej[b+1] = ej[b]; b--; }
        ei[b+1] = ki; ej[b+1] = kj;
    }
    int nr = 0, ncl = 0;
    int rows[MAXR], cols[MAXR];
    int e;
    for (e = 0; e < ne; e++) {
        int r = -1; for (int q = 0; q < nr;  q++) if (rows[q] == ei[e]) r = q;
        int c = -1; for (int q = 0; q < ncl; q++) if (cols[q] == ej[e]) c = q;
        if (r < 0 && nr  >= MAXR) break;
        if (c < 0 && ncl >= MAXR) break;
        if (r < 0) { r = nr;  rows[nr++]  = ei[e]; }
        if (c < 0) { c = ncl; cols[ncl++] = ej[e]; }
        Ei[e] = ei[e]; Ej[e] = ej[e]; Er[e] = r; Ec[e] = c;
    }
    *ne_o = e; *nr_o = nr; *nc_o = ncl;
    for (int q = 0; q < nr;  q++) Rows[q] = rows[q];
    for (int q = 0; q < ncl; q++) Cols[q] = cols[q];
}

// ---------------- k_vvt: A = V V^T + per-block candidate push ---------------
__global__ void __launch_bounds__(256) k_vvt(const float* __restrict__ V) {
    __shared__ float sI[32][33], sJ[32][33];
    __shared__ unsigned sHist[2048];
    __shared__ unsigned sPart[256];
    __shared__ int sSelbin;
    int i0 = blockIdx.y * 32, j0 = blockIdx.x * 32;
    int t = threadIdx.x;
    int ty = t >> 4, tx = t & 15;
    for (int e = t; e < 2048; e += 256) sHist[e] = 0u;
    float c00 = 0, c01 = 0, c10 = 0, c11 = 0;
    for (int k0 = 0; k0 < HF; k0 += 32) {
        __syncthreads();
        for (int e = t; e < 1024; e += 256) {
            int r = e >> 5, c = e & 31;
            sI[r][c] = V[(i0 + r) * HF + k0 + c];
            sJ[r][c] = V[(j0 + r) * HF + k0 + c];
        }
        __syncthreads();
#pragma unroll
        for (int k = 0; k < 32; k++) {
            float a0 = sI[2 * ty][k],     a1 = sI[2 * ty + 1][k];
            float b0 = sJ[2 * tx][k],     b1 = sJ[2 * tx + 1][k];
            c00 += a0 * b0; c01 += a0 * b1; c10 += a1 * b0; c11 += a1 * b1;
        }
    }
    int r0 = i0 + 2 * ty, cc0 = j0 + 2 * tx;
    g_A[(r0)     * NN + cc0]     = c00;
    g_A[(r0)     * NN + cc0 + 1] = c01;
    g_A[(r0 + 1) * NN + cc0]     = c10;
    g_A[(r0 + 1) * NN + cc0 + 1] = c11;
    unsigned keys[4] = {fkey(c00), fkey(c01), fkey(c10), fkey(c11)};
    atomicAdd(&sHist[keys[0] >> 21], 1u);
    atomicAdd(&sHist[keys[1] >> 21], 1u);
    atomicAdd(&sHist[keys[2] >> 21], 1u);
    atomicAdd(&sHist[keys[3] >> 21], 1u);
    __syncthreads();
    // suffix sums over 2048 bins (8 per thread)
    unsigned loc = 0;
#pragma unroll
    for (int q = 0; q < 8; q++) loc += sHist[t * 8 + q];
    sPart[t] = loc;
    __syncthreads();
    for (int off = 1; off < 256; off <<= 1) {
        unsigned v = (t + off < 256) ? sPart[t + off] : 0u;
        __syncthreads();
        sPart[t] += v;
        __syncthreads();
    }
    unsigned cum = (t < 255) ? sPart[t + 1] : 0u;    // count in bins above mine
    for (int b = t * 8 + 7; b >= t * 8; b--) {
        unsigned c2 = cum + sHist[b];
        if (cum < TOPK && c2 >= TOPK) sSelbin = b;   // exactly one thread writes
        cum = c2;
    }
    __syncthreads();
    unsigned sb = (unsigned)sSelbin;
    // push every value in bins >= sb (superset of block top-12)
#pragma unroll
    for (int q = 0; q < 4; q++) {
        if ((keys[q] >> 21) >= sb) {
            int pos = atomicAdd(&g_nc2, 1);
            if (pos < CAND_CAP) g_cand2[pos] = keys[q];
        }
    }
}

// ---------------- k_adj: per-block exact kth; write adj; append edges -------
__global__ void __launch_bounds__(256) k_adj(float* __restrict__ adj_out) {
    __shared__ unsigned sKth;
    int t = threadIdx.x, b = blockIdx.x;
    if (b == 0) {                                     // zero output accumulator
        for (int e = t; e < MAXR * NC; e += 256) g_WhOut[e] = 0.f;
    }
    if (t < 32) {                                     // warp 0: exact 12th largest
        int n = g_nc2; if (n > CAND_CAP) n = CAND_CAP;
        unsigned top[TOPK];
#pragma unroll
        for (int s = 0; s < TOPK; s++) top[s] = 0u;
        for (int i = t; i < n; i += 32) {
            unsigned k = g_cand2[i];
            if (k > top[TOPK - 1]) {
                top[TOPK - 1] = k;
#pragma unroll
                for (int s = TOPK - 1; s > 0; s--)
                    if (top[s] > top[s - 1]) { unsigned tmp = top[s]; top[s] = top[s - 1]; top[s - 1] = tmp; }
            }
        }
        unsigned kth = 0;
        for (int it = 0; it < TOPK; it++) {
            unsigned gm = __reduce_max_sync(0xffffffffu, top[0]);
            kth = gm;
            unsigned bal = __ballot_sync(0xffffffffu, top[0] == gm);
            if (t == (__ffs(bal) - 1)) {
#pragma unroll
                for (int s = 0; s < TOPK - 1; s++) top[s] = top[s + 1];
                top[TOPK - 1] = 0u;
            }
        }
        if (t == 0) sKth = kth;
    }
    __syncthreads();
    unsigned kth = sKth;
    int idx = (b * 256 + t) * 4;
    float4 v = *(const float4*)&g_A[idx];
    float vv[4] = {v.x, v.y, v.z, v.w};
    float ov[4];
#pragma unroll
    for (int q = 0; q < 4; q++) {
        bool on = fkey(vv[q]) > kth;
        ov[q] = on ? 1.f : 0.f;
        if (on) {
            int s = atomicAdd(&g_ne_raw, 1);
            if (s < MAXE) { g_ei_raw[s] = (idx + q) >> 9; g_ej_raw[s] = (idx + q) & 511; }
        }
    }
    if (adj_out) *(float4*)&adj_out[idx] = make_float4(ov[0], ov[1], ov[2], ov[3]);
}

// ---------------- k_head: stream W_stack once (register-staged) -------------
__global__ void __launch_bounds__(256) k_head(const float* __restrict__ X,
                                              const float* __restrict__ Wst,
                                              const float* __restrict__ ast) {
    __shared__ float sW[64 * 68];        // [f][k] stride 68
    __shared__ float sXc[MAXR][260];
    __shared__ float sA[128];
    __shared__ int sNe, sNr, sNc, sEi[MAXE], sEj[MAXE], sEr[MAXE], sEc[MAXE];
    __shared__ int sRows[MAXR], sCols[MAXR];
    int h = blockIdx.x, t = threadIdx.x;
    if (h == 0 && t == 0) g_nc2 = 0;     // reset for next replay (adj done)
    const float4* W4 = (const float4*)(Wst + (size_t)h * FIN * HF);
    float4 st[4];
#pragma unroll
    for (int q = 0; q < 4; q++) st[q] = W4[q * 256 + t];
    if (t < 128) sA[t] = ast[h * 128 + t];
    if (t == 0) prep0(&sNe, &sNr, &sNc, sEi, sEj, sEr, sEc, sRows, sCols);
    __syncthreads();
    int ncols = sNc;
    for (int e = t; e < MAXR * 256; e += 256) {
        int c = e >> 8, f = e & 255;
        sXc[c][f] = (c < ncols) ? X[sCols[c] * FIN + f] : 0.f;
    }
    int j = t >> 4, kq = t & 15;
    int fdot = t >> 2, qq = t & 3, kd0 = qq * 16;
    float acc[4] = {0.f, 0.f, 0.f, 0.f};
    for (int ft = 0; ft < 4; ft++) {
#pragma unroll
        for (int q = 0; q < 4; q++) {
            int flat = 4 * (q * 256 + t);
            int fl = flat >> 6, k = flat & 63;
            *(float4*)&sW[fl * 68 + k] = st[q];
        }
        __syncthreads();
        if (ft < 3) {
#pragma unroll
            for (int q = 0; q < 4; q++) st[q] = W4[(ft + 1) * 1024 + q * 256 + t];
        }
        {   // w1/w2 dots for this tile's 64 f rows
            float s1 = 0.f, s2 = 0.f;
#pragma unroll
            for (int k = 0; k < 16; k++) {
                float w = sW[fdot * 68 + kd0 + k];
                s1 += w * sA[kd0 + k];
                s2 += w * sA[64 + kd0 + k];
            }
            s1 += __shfl_xor_sync(~0u, s1, 1); s2 += __shfl_xor_sync(~0u, s2, 1);
            s1 += __shfl_xor_sync(~0u, s1, 2); s2 += __shfl_xor_sync(~0u, s2, 2);
            if (qq == 0) {
                g_w1[h * FIN + ft * 64 + fdot] = s1;
                g_w2[h * FIN + ft * 64 + fdot] = s2;
            }
        }
        if (j < ncols) {
#pragma unroll 8
            for (int f = 0; f < 64; f++) {
                float x = sXc[j][ft * 64 + f];
                float4 w = *(const float4*)&sW[f * 68 + kq * 4];
                acc[0] += x * w.x; acc[1] += x * w.y; acc[2] += x * w.z; acc[3] += x * w.w;
            }
        }
        __syncthreads();
    }
    if (j < ncols) {
        *(float4*)&g_WhN[((size_t)h * MAXR + j) * HF + kq * 4] =
            make_float4(acc[0], acc[1], acc[2], acc[3]);
    }
}

// ---------------- k_e2: E2T[h][j] = sum_f w2[h][f] * X[j][f] ----------------
__global__ void __launch_bounds__(256) k_e2(const float* __restrict__ X) {
    __shared__ float sA2[32 * 33], sB2[32 * 33];
    int h0 = blockIdx.y * 32, j0 = blockIdx.x * 32;
    int t = threadIdx.x;
    int ty = t >> 4, tx = t & 15;
    float c00 = 0, c01 = 0, c10 = 0, c11 = 0;
    for (int f0 = 0; f0 < FIN; f0 += 32) {
        __syncthreads();
        for (int e = t; e < 1024; e += 256) {
            int r = e >> 5, f = e & 31;
            sA2[r * 33 + f] = g_w2[(h0 + r) * FIN + f0 + f];
            sB2[r * 33 + f] = X[(j0 + r) * FIN + f0 + f];
        }
        __syncthreads();
#pragma unroll
        for (int f = 0; f < 32; f++) {
            float a0 = sA2[(2 * ty) * 33 + f],     a1 = sA2[(2 * ty + 1) * 33 + f];
            float b0 = sB2[(2 * tx) * 33 + f],     b1 = sB2[(2 * tx + 1) * 33 + f];
            c00 += a0 * b0; c01 += a0 * b1; c10 += a1 * b0; c11 += a1 * b1;
        }
    }
    g_E2T[(h0 + 2 * ty) * NN + j0 + 2 * tx]         = c00;
    g_E2T[(h0 + 2 * ty) * NN + j0 + 2 * tx + 1]     = c01;
    g_E2T[(h0 + 2 * ty + 1) * NN + j0 + 2 * tx]     = c10;
    g_E2T[(h0 + 2 * ty + 1) * NN + j0 + 2 * tx + 1] = c11;
}

// ---------------- k_epi: softmax rows + mid + fused mid@Wout ----------------
__global__ void __launch_bounds__(256) k_epi(const float* __restrict__ X,
                                             const float* __restrict__ Wout) {
    __shared__ float sE2[512];
    __shared__ float sE1a[MAXR], sM[MAXR], sDi[MAXR];
    __shared__ float sOut[MAXR * 64];
    __shared__ float sRed[8];
    __shared__ float sMax;
    __shared__ float sPartM[4][MAXR * 64];   // 16KB partials for mid@Wout
    __shared__ int sNe, sNr, sNc, sEi[MAXE], sEj[MAXE], sEr[MAXE], sEc[MAXE];
    __shared__ int sRows[MAXR], sCols[MAXR];
    int h = blockIdx.x, t = threadIdx.x;
    if (t == 0) prep0(&sNe, &sNr, &sNc, sEi, sEj, sEr, sEc, sRows, sCols);
    sE2[t]       = g_E2T[h * NN + t];
    sE2[t + 256] = g_E2T[h * NN + t + 256];
    int wid = t >> 5, lane = t & 31;
    float m = fmaxf(sE2[t], sE2[t + 256]);       // own values
    for (int o = 16; o; o >>= 1) m = fmaxf(m, __shfl_xor_sync(~0u, m, o));
    if (lane == 0) sRed[wid] = m;
    for (int e = t; e < MAXR * 64; e += 256) sOut[e] = 0.f;
    __syncthreads();                              // prep, sE2, sRed visible
    int nrows = sNr, ne = sNe;
    if (t == 0) {
        float mm = sRed[0];
        for (int w = 1; w < 8; w++) mm = fmaxf(mm, sRed[w]);
        sMax = mm;
    }
    // e1 at active rows: warp per row (2 rows/warp)
    float e1v[2] = {0.f, 0.f};
#pragma unroll
    for (int rr = 0; rr < 2; rr++) {
        int r = wid + 8 * rr;
        if (r < nrows) {
            int i = sRows[r];
            float s = 0.f;
            for (int f = lane; f < FIN; f += 32) s += X[i * FIN + f] * g_w1[h * FIN + f];
            for (int o = 16; o; o >>= 1) s += __shfl_xor_sync(~0u, s, o);
            e1v[rr] = s;
            if (lane == 0) sE1a[r] = s;
        }
    }
    __syncthreads();
    float e2max = sMax;
#pragma unroll
    for (int rr = 0; rr < 2; rr++) {
        int r = wid + 8 * rr;
        if (r < nrows) {
            float e1 = e1v[rr];
            float mr = lrelu(e1 + e2max);
            float p = 0.f;
            for (int c = lane; c < NN; c += 32) p += __expf(lrelu(e1 + sE2[c]) - mr);
            for (int o = 16; o; o >>= 1) p += __shfl_xor_sync(~0u, p, o);
            if (lane == 0) { sM[r] = mr; sDi[r] = 1.f / p; }
        }
    }
    __syncthreads();
    // sparse A @ Wh over edges
    if (t < 64) {
        for (int e = 0; e < ne; e++) {
            int r = sEr[e], ci = sEc[e], jj = sEj[e];
            float alpha = __expf(lrelu(sE1a[r] + sE2[jj]) - sM[r]) * sDi[r];
            sOut[r * 64 + t] += alpha * g_WhN[((size_t)h * MAXR + ci) * HF + t];
        }
    }
    __syncthreads();
    // elu in place -> mid activations
    for (int e = t; e < MAXR * 64; e += 256) {
        int r = e >> 6;
        if (r < nrows) sOut[e] = elu1(sOut[e]);
    }
    __syncthreads();
    // fused mid@Wout: this block owns Wout rows [h*64, h*64+64)
    int c = t & 63, kq = t >> 6;
    float part[MAXR];
#pragma unroll
    for (int r = 0; r < MAXR; r++) part[r] = 0.f;
    for (int k = kq * 16; k < kq * 16 + 16; k++) {
        float w = Wout[(size_t)(h * 64 + k) * NC + c];
#pragma unroll
        for (int r = 0; r < MAXR; r++)
            if (r < nrows) part[r] += sOut[r * 64 + k] * w;   // sOut broadcast
    }
#pragma unroll
    for (int r = 0; r < MAXR; r++)
        if (r < nrows) sPartM[kq][r * 64 + c] = part[r];
    __syncthreads();
    if (kq == 0) {
        for (int r = 0; r < nrows; r++) {
            float s = sPartM[0][r * 64 + c] + sPartM[1][r * 64 + c]
                    + sPartM[2][r * 64 + c] + sPartM[3][r * 64 + c];
            atomicAdd(&g_WhOut[r * 64 + c], s);
        }
    }
}

// ---------------- k_final: output GAT layer + elu(V*out), full write --------
__global__ void __launch_bounds__(512) k_final(const float* __restrict__ V,
                                               const float* __restrict__ aout,
                                               float* __restrict__ outp) {
    __shared__ float sAo[128];
    __shared__ float e1o[MAXR], e2o[MAXR];
    __shared__ float sAlpha[MAXE];
    __shared__ int   sJr[MAXE];
    __shared__ int   sRowOf[NN];
    __shared__ int sNe, sNr, sNc, sEi[MAXE], sEj[MAXE], sEr[MAXE], sEc[MAXE];
    __shared__ int sRows[MAXR], sCols[MAXR];
    int t = threadIdx.x;
    if (t == 0) prep0(&sNe, &sNr, &sNc, sEi, sEj, sEr, sEc, sRows, sCols);
    if (t < 128) sAo[t] = aout[t];
    for (int e = t; e < NN; e += 512) sRowOf[e] = -1;
    __syncthreads();
    int nrows = sNr, ne = sNe;
    if (t < nrows) sRowOf[sRows[t]] = t;
    int wid = t >> 5, lane = t & 31;
    if (wid < MAXR && wid < nrows) {
        int r = wid;
        float w0 = g_WhOut[r * NC + lane];
        float w1 = g_WhOut[r * NC + 32 + lane];
        float s1 = w0 * sAo[lane]      + w1 * sAo[32 + lane];
        float s2 = w0 * sAo[64 + lane] + w1 * sAo[96 + lane];
        for (int o = 16; o; o >>= 1) {
            s1 += __shfl_xor_sync(~0u, s1, o);
            s2 += __shfl_xor_sync(~0u, s2, o);
        }
        if (lane == 0) { e1o[r] = s1; e2o[r] = s2; }
    }
    __syncthreads();
    if (t == 0) {
        float mm2[MAXR], d2[MAXR];
        float e2m = 0.f;   // inactive rows contribute e2 == 0 exactly
        for (int r = 0; r < nrows; r++) e2m = fmaxf(e2m, e2o[r]);
        for (int r = 0; r < nrows; r++) {
            float mm = lrelu(e1o[r] + e2m);
            float D = (float)(NN - nrows) * __expf(lrelu(e1o[r]) - mm);
            for (int q = 0; q < nrows; q++) D += __expf(lrelu(e1o[r] + e2o[q]) - mm);
            mm2[r] = mm; d2[r] = 1.f / D;
        }
        for (int ed = 0; ed < ne; ed++) {
            int r = sEr[ed];
            int jr = sRowOf[sEj[ed]];
            sJr[ed] = jr;
            sAlpha[ed] = (jr >= 0)
                ? __expf(lrelu(e1o[r] + e2o[jr]) - mm2[r]) * d2[r]
                : 0.f;                    // Wh_out[j]==0 -> no contribution
        }
    }
    __syncthreads();
    if (outp) {
        for (int idx = t; idx < NN * NC; idx += 512) {
            int i = idx >> 6, k = idx & 63;
            int r = sRowOf[i];
            float val = 0.f;
            if (r >= 0) {
                float o2 = 0.f;
                for (int ed = 0; ed < ne; ed++)
                    if (sEr[ed] == r && sJr[ed] >= 0)
                        o2 += sAlpha[ed] * g_WhOut[sJr[ed] * NC + k];
                val = elu1(V[idx] * elu1(o2));
            }
            outp[idx] = val;
        }
    }
    __syncthreads();
    if (t == 0) g_ne_raw = 0;             // reset for next replay
}

// ---------------- host ------------------------------------------------------
extern "C" void kernel_launch(void* const* d_in, const int* in_sizes, int n_in,
                              void* d_out, int out_size) {
    const float* X    = (const float*)d_in[0];
    const float* Wst  = (const float*)d_in[1];
    const float* ast  = (const float*)d_in[2];
    const float* Wout = (const float*)d_in[3];
    const float* aout = (const float*)d_in[4];
    const float* V    = (const float*)d_in[5];
    float* outbuf = (float*)d_out;

    float* adj_dst  = nullptr;
    float* feat_dst = nullptr;
    if (out_size >= NN * NN + NN * NC) { adj_dst = outbuf; feat_dst = outbuf + NN * NN; }
    else if (out_size == NN * NN)      { adj_dst = outbuf; }
    else                               { feat_dst = outbuf; }

    k_vvt   <<<dim3(16, 16), 256>>>(V);
    k_adj   <<<256, 256>>>(adj_dst);
    k_head  <<<512, 256>>>(X, Wst, ast);
    k_e2    <<<dim3(16, 16), 256>>>(X);
    k_epi   <<<512, 256>>>(X, Wout);
    k_final <<<1, 512>>>(V, aout, feat_dst);
}

// round 16
// speedup vs baseline: 1.3475x; 1.3475x over previous
#include <cuda_runtime.h>
#include <math.h>
#include <float.h>

#define NN    512
#define FIN   256
#define HF    64
#define NC    64
#define TOPK  12
#define LALPHA 0.2f
#define MAXE  32
#define MAXR  16   // max distinct rows/cols (math guarantees <= 11)
#define CAND_CAP 8192

// ---------------- scratch (device globals; zero-initialized) ----------------
__device__ float    g_A[NN * NN];
__device__ int      g_nc2;                 // candidate count (reset by k_head)
__device__ unsigned g_cand2[CAND_CAP];
__device__ int      g_ne_raw;              // edge count (reset by next k_vvt)
__device__ int      g_ei_raw[MAXE], g_ej_raw[MAXE];
__device__ float    g_w1[NN * FIN];
__device__ float    g_w2[NN * FIN];
__device__ float    g_WhN[(size_t)NN * MAXR * HF];   // [h][colidx][k]
__device__ float    g_E2T[NN * NN];                  // [h][j]
__device__ float    g_WhOut[MAXR * NC];              // zeroed by k_adj blk0

__device__ __forceinline__ float lrelu(float x) { return x >= 0.f ? x : LALPHA * x; }
__device__ __forceinline__ float elu1(float x)  { return x > 0.f ? x : expm1f(x); }
__device__ __forceinline__ unsigned fkey(float f) {
    unsigned u = __float_as_uint(f);
    return (u & 0x80000000u) ? ~u : (u | 0x80000000u);
}

// ---- warp-parallel prep: lanes sort edges + dedup rows/cols (no local mem) -
// Must be called by full warp (32 lanes). Produces ordering identical to the
// serial sort+first-appearance dedup.
__device__ __forceinline__ void warp_prep(int lane,
        int* sNe, int* sNr, int* sNc,
        int* sEi, int* sEj, int* sEr, int* sEc,
        int* sRows, int* sCols) {
    const unsigned full = 0xffffffffu;
    int ne = g_ne_raw; if (ne > MAXE) ne = MAXE;
    int key = (lane < ne) ? (g_ei_raw[lane] * NN + g_ej_raw[lane]) : 0x7fffffff;
    // bitonic sort ascending across 32 lanes
#pragma unroll
    for (int k = 2; k <= 32; k <<= 1) {
#pragma unroll
        for (int j = k >> 1; j > 0; j >>= 1) {
            int other = __shfl_xor_sync(full, key, j);
            bool keepmin = (((lane & j) == 0) == ((lane & k) == 0));
            key = keepmin ? min(key, other) : max(key, other);
        }
    }
    int ei = key >> 9, ej = key & 511;
    bool act = lane < ne;
    unsigned pr = __match_any_sync(full, ei);
    int fr = __ffs(pr) - 1;
    unsigned rlead = __ballot_sync(full, act && lane == fr);
    int rid = __popc(rlead & ((2u << fr) - 1)) - 1;
    unsigned pc = __match_any_sync(full, ej);
    int fc = __ffs(pc) - 1;
    unsigned clead = __ballot_sync(full, act && lane == fc);
    int cid = __popc(clead & ((2u << fc) - 1)) - 1;
    if (act) {
        sEi[lane] = ei; sEj[lane] = ej; sEr[lane] = rid; sEc[lane] = cid;
        if (lane == fr && rid >= 0 && rid < MAXR) sRows[rid] = ei;
        if (lane == fc && cid >= 0 && cid < MAXR) sCols[cid] = ej;
    }
    if (lane == 0) {
        *sNe = ne;
        int nr = __popc(rlead); *sNr = nr > MAXR ? MAXR : nr;
        int nc = __popc(clead); *sNc = nc > MAXR ? MAXR : nc;
    }
}

// ---------------- k_vvt: A = V V^T + per-block candidate push ---------------
__global__ void __launch_bounds__(256) k_vvt(const float* __restrict__ V) {
    __shared__ float sI[32][33], sJ[32][33];
    __shared__ unsigned sHist[2048];
    __shared__ unsigned sPart[256];
    __shared__ int sSelbin;
    int i0 = blockIdx.y * 32, j0 = blockIdx.x * 32;
    int t = threadIdx.x;
    if (blockIdx.x == 0 && blockIdx.y == 0 && t == 0) g_ne_raw = 0; // reset for this replay's k_adj
    int ty = t >> 4, tx = t & 15;
    for (int e = t; e < 2048; e += 256) sHist[e] = 0u;
    float c00 = 0, c01 = 0, c10 = 0, c11 = 0;
    for (int k0 = 0; k0 < HF; k0 += 32) {
        __syncthreads();
        for (int e = t; e < 1024; e += 256) {
            int r = e >> 5, c = e & 31;
            sI[r][c] = V[(i0 + r) * HF + k0 + c];
            sJ[r][c] = V[(j0 + r) * HF + k0 + c];
        }
        __syncthreads();
#pragma unroll
        for (int k = 0; k < 32; k++) {
            float a0 = sI[2 * ty][k],     a1 = sI[2 * ty + 1][k];
            float b0 = sJ[2 * tx][k],     b1 = sJ[2 * tx + 1][k];
            c00 += a0 * b0; c01 += a0 * b1; c10 += a1 * b0; c11 += a1 * b1;
        }
    }
    int r0 = i0 + 2 * ty, cc0 = j0 + 2 * tx;
    g_A[(r0)     * NN + cc0]     = c00;
    g_A[(r0)     * NN + cc0 + 1] = c01;
    g_A[(r0 + 1) * NN + cc0]     = c10;
    g_A[(r0 + 1) * NN + cc0 + 1] = c11;
    unsigned keys[4] = {fkey(c00), fkey(c01), fkey(c10), fkey(c11)};
    atomicAdd(&sHist[keys[0] >> 21], 1u);
    atomicAdd(&sHist[keys[1] >> 21], 1u);
    atomicAdd(&sHist[keys[2] >> 21], 1u);
    atomicAdd(&sHist[keys[3] >> 21], 1u);
    __syncthreads();
    unsigned loc = 0;
#pragma unroll
    for (int q = 0; q < 8; q++) loc += sHist[t * 8 + q];
    sPart[t] = loc;
    __syncthreads();
    for (int off = 1; off < 256; off <<= 1) {
        unsigned v = (t + off < 256) ? sPart[t + off] : 0u;
        __syncthreads();
        sPart[t] += v;
        __syncthreads();
    }
    unsigned cum = (t < 255) ? sPart[t + 1] : 0u;
    for (int b = t * 8 + 7; b >= t * 8; b--) {
        unsigned c2 = cum + sHist[b];
        if (cum < TOPK && c2 >= TOPK) sSelbin = b;
        cum = c2;
    }
    __syncthreads();
    unsigned sb = (unsigned)sSelbin;
#pragma unroll
    for (int q = 0; q < 4; q++) {
        if ((keys[q] >> 21) >= sb) {
            int pos = atomicAdd(&g_nc2, 1);
            if (pos < CAND_CAP) g_cand2[pos] = keys[q];
        }
    }
}

// ---------------- k_adj: per-block exact kth; write adj; append edges -------
__global__ void __launch_bounds__(256) k_adj(float* __restrict__ adj_out) {
    __shared__ unsigned sKth;
    int t = threadIdx.x, b = blockIdx.x;
    if (b == 0) {
        for (int e = t; e < MAXR * NC; e += 256) g_WhOut[e] = 0.f;
    }
    if (t < 32) {
        int n = g_nc2; if (n > CAND_CAP) n = CAND_CAP;
        unsigned top[TOPK];
#pragma unroll
        for (int s = 0; s < TOPK; s++) top[s] = 0u;
        for (int i = t; i < n; i += 32) {
            unsigned k = g_cand2[i];
            if (k > top[TOPK - 1]) {
                top[TOPK - 1] = k;
#pragma unroll
                for (int s = TOPK - 1; s > 0; s--)
                    if (top[s] > top[s - 1]) { unsigned tmp = top[s]; top[s] = top[s - 1]; top[s - 1] = tmp; }
            }
        }
        unsigned kth = 0;
        for (int it = 0; it < TOPK; it++) {
            unsigned gm = __reduce_max_sync(0xffffffffu, top[0]);
            kth = gm;
            unsigned bal = __ballot_sync(0xffffffffu, top[0] == gm);
            if (t == (__ffs(bal) - 1)) {
#pragma unroll
                for (int s = 0; s < TOPK - 1; s++) top[s] = top[s + 1];
                top[TOPK - 1] = 0u;
            }
        }
        if (t == 0) sKth = kth;
    }
    __syncthreads();
    unsigned kth = sKth;
    int idx = (b * 256 + t) * 4;
    float4 v = *(const float4*)&g_A[idx];
    float vv[4] = {v.x, v.y, v.z, v.w};
    float ov[4];
#pragma unroll
    for (int q = 0; q < 4; q++) {
        bool on = fkey(vv[q]) > kth;
        ov[q] = on ? 1.f : 0.f;
        if (on) {
            int s = atomicAdd(&g_ne_raw, 1);
            if (s < MAXE) { g_ei_raw[s] = (idx + q) >> 9; g_ej_raw[s] = (idx + q) & 511; }
        }
    }
    if (adj_out) *(float4*)&adj_out[idx] = make_float4(ov[0], ov[1], ov[2], ov[3]);
}

// ---------------- k_head: stream W_stack once (register-staged) -------------
__global__ void __launch_bounds__(256) k_head(const float* __restrict__ X,
                                              const float* __restrict__ Wst,
                                              const float* __restrict__ ast) {
    __shared__ float sW[64 * 68];
    __shared__ float sXc[MAXR][260];
    __shared__ float sA[128];
    __shared__ int sNe, sNr, sNc, sEi[MAXE], sEj[MAXE], sEr[MAXE], sEc[MAXE];
    __shared__ int sRows[MAXR], sCols[MAXR];
    int h = blockIdx.x, t = threadIdx.x;
    if (h == 0 && t == 0) g_nc2 = 0;     // reset for next replay (adj done)
    const float4* W4 = (const float4*)(Wst + (size_t)h * FIN * HF);
    float4 st[4];
#pragma unroll
    for (int q = 0; q < 4; q++) st[q] = W4[q * 256 + t];
    if (t < 128) sA[t] = ast[h * 128 + t];
    if (t < 32) warp_prep(t, &sNe, &sNr, &sNc, sEi, sEj, sEr, sEc, sRows, sCols);
    __syncthreads();
    int ncols = sNc;
    for (int e = t; e < MAXR * 256; e += 256) {
        int c = e >> 8, f = e & 255;
        sXc[c][f] = (c < ncols) ? X[sCols[c] * FIN + f] : 0.f;
    }
    int j = t >> 4, kq = t & 15;
    int fdot = t >> 2, qq = t & 3, kd0 = qq * 16;
    float acc[4] = {0.f, 0.f, 0.f, 0.f};
    for (int ft = 0; ft < 4; ft++) {
#pragma unroll
        for (int q = 0; q < 4; q++) {
            int flat = 4 * (q * 256 + t);
            int fl = flat >> 6, k = flat & 63;
            *(float4*)&sW[fl * 68 + k] = st[q];
        }
        __syncthreads();
        if (ft < 3) {
#pragma unroll
            for (int q = 0; q < 4; q++) st[q] = W4[(ft + 1) * 1024 + q * 256 + t];
        }
        {
            float s1 = 0.f, s2 = 0.f;
#pragma unroll
            for (int k = 0; k < 16; k++) {
                float w = sW[fdot * 68 + kd0 + k];
                s1 += w * sA[kd0 + k];
                s2 += w * sA[64 + kd0 + k];
            }
            s1 += __shfl_xor_sync(~0u, s1, 1); s2 += __shfl_xor_sync(~0u, s2, 1);
            s1 += __shfl_xor_sync(~0u, s1, 2); s2 += __shfl_xor_sync(~0u, s2, 2);
            if (qq == 0) {
                g_w1[h * FIN + ft * 64 + fdot] = s1;
                g_w2[h * FIN + ft * 64 + fdot] = s2;
            }
        }
        if (j < ncols) {
#pragma unroll 8
            for (int f = 0; f < 64; f++) {
                float x = sXc[j][ft * 64 + f];
                float4 w = *(const float4*)&sW[f * 68 + kq * 4];
                acc[0] += x * w.x; acc[1] += x * w.y; acc[2] += x * w.z; acc[3] += x * w.w;
            }
        }
        __syncthreads();
    }
    if (j < ncols) {
        *(float4*)&g_WhN[((size_t)h * MAXR + j) * HF + kq * 4] =
            make_float4(acc[0], acc[1], acc[2], acc[3]);
    }
}

// ---------------- k_e2: E2T[h][j] = sum_f w2[h][f] * X[j][f] ----------------
// 32x32 tile, 128 threads, 4(h) x 2(j) per thread, transposed smem.
__global__ void __launch_bounds__(128) k_e2(const float* __restrict__ X) {
    __shared__ float sA2[32][36];   // [k][h]
    __shared__ float sB2[32][36];   // [k][j]
    int h0 = blockIdx.y * 32, j0 = blockIdx.x * 32;
    int t = threadIdx.x;
    int tx = t & 15, ty = t >> 4;   // tx: j/2, ty: h/4
    float a00=0,a01=0,a10=0,a11=0,a20=0,a21=0,a30=0,a31=0;
    for (int f0 = 0; f0 < FIN; f0 += 32) {
        __syncthreads();
#pragma unroll
        for (int q = 0; q < 8; q++) {
            int e = q * 128 + t;
            int r = e >> 5, k = e & 31;
            sA2[k][r] = g_w2[(h0 + r) * FIN + f0 + k];
            sB2[k][r] = X[(j0 + r) * FIN + f0 + k];
        }
        __syncthreads();
#pragma unroll
        for (int k = 0; k < 32; k++) {
            float4 a = *(const float4*)&sA2[k][ty * 4];
            float2 b = *(const float2*)&sB2[k][tx * 2];
            a00 += a.x * b.x; a01 += a.x * b.y;
            a10 += a.y * b.x; a11 += a.y * b.y;
            a20 += a.z * b.x; a21 += a.z * b.y;
            a30 += a.w * b.x; a31 += a.w * b.y;
        }
    }
    int jb = j0 + tx * 2;
    *(float2*)&g_E2T[(h0 + ty * 4 + 0) * NN + jb] = make_float2(a00, a01);
    *(float2*)&g_E2T[(h0 + ty * 4 + 1) * NN + jb] = make_float2(a10, a11);
    *(float2*)&g_E2T[(h0 + ty * 4 + 2) * NN + jb] = make_float2(a20, a21);
    *(float2*)&g_E2T[(h0 + ty * 4 + 3) * NN + jb] = make_float2(a30, a31);
}

// ---------------- k_epi: softmax rows + mid + fused mid@Wout ----------------
__global__ void __launch_bounds__(256) k_epi(const float* __restrict__ X,
                                             const float* __restrict__ Wout) {
    __shared__ float sE2[512];
    __shared__ float sE1a[MAXR], sM[MAXR], sDi[MAXR];
    __shared__ float sOut[MAXR * 64];
    __shared__ float sRed[8];
    __shared__ float sMax;
    __shared__ float sPartM[4][MAXR * 64];
    __shared__ int sNe, sNr, sNc, sEi[MAXE], sEj[MAXE], sEr[MAXE], sEc[MAXE];
    __shared__ int sRows[MAXR], sCols[MAXR];
    int h = blockIdx.x, t = threadIdx.x;
    if (t < 32) warp_prep(t, &sNe, &sNr, &sNc, sEi, sEj, sEr, sEc, sRows, sCols);
    sE2[t]       = g_E2T[h * NN + t];
    sE2[t + 256] = g_E2T[h * NN + t + 256];
    int wid = t >> 5, lane = t & 31;
    float m = fmaxf(sE2[t], sE2[t + 256]);
    for (int o = 16; o; o >>= 1) m = fmaxf(m, __shfl_xor_sync(~0u, m, o));
    if (lane == 0) sRed[wid] = m;
    for (int e = t; e < MAXR * 64; e += 256) sOut[e] = 0.f;
    __syncthreads();
    int nrows = sNr, ne = sNe;
    if (t == 0) {
        float mm = sRed[0];
        for (int w = 1; w < 8; w++) mm = fmaxf(mm, sRed[w]);
        sMax = mm;
    }
    float e1v[2] = {0.f, 0.f};
#pragma unroll
    for (int rr = 0; rr < 2; rr++) {
        int r = wid + 8 * rr;
        if (r < nrows) {
            int i = sRows[r];
            float s = 0.f;
            for (int f = lane; f < FIN; f += 32) s += X[i * FIN + f] * g_w1[h * FIN + f];
            for (int o = 16; o; o >>= 1) s += __shfl_xor_sync(~0u, s, o);
            e1v[rr] = s;
            if (lane == 0) sE1a[r] = s;
        }
    }
    __syncthreads();
    float e2max = sMax;
#pragma unroll
    for (int rr = 0; rr < 2; rr++) {
        int r = wid + 8 * rr;
        if (r < nrows) {
            float e1 = e1v[rr];
            float mr = lrelu(e1 + e2max);
            float p = 0.f;
            for (int c = lane; c < NN; c += 32) p += __expf(lrelu(e1 + sE2[c]) - mr);
            for (int o = 16; o; o >>= 1) p += __shfl_xor_sync(~0u, p, o);
            if (lane == 0) { sM[r] = mr; sDi[r] = 1.f / p; }
        }
    }
    __syncthreads();
    if (t < 64) {
        for (int e = 0; e < ne; e++) {
            int r = sEr[e], ci = sEc[e], jj = sEj[e];
            float alpha = __expf(lrelu(sE1a[r] + sE2[jj]) - sM[r]) * sDi[r];
            sOut[r * 64 + t] += alpha * g_WhN[((size_t)h * MAXR + ci) * HF + t];
        }
    }
    __syncthreads();
    for (int e = t; e < MAXR * 64; e += 256) {
        int r = e >> 6;
        if (r < nrows) sOut[e] = elu1(sOut[e]);
    }
    __syncthreads();
    int c = t & 63, kq = t >> 6;
    float part[MAXR];
#pragma unroll
    for (int r = 0; r < MAXR; r++) part[r] = 0.f;
    for (int k = kq * 16; k < kq * 16 + 16; k++) {
        float w = Wout[(size_t)(h * 64 + k) * NC + c];
#pragma unroll
        for (int r = 0; r < MAXR; r++)
            if (r < nrows) part[r] += sOut[r * 64 + k] * w;
    }
#pragma unroll
    for (int r = 0; r < MAXR; r++)
        if (r < nrows) sPartM[kq][r * 64 + c] = part[r];
    __syncthreads();
    if (kq == 0) {
        for (int r = 0; r < nrows; r++) {
            float s = sPartM[0][r * 64 + c] + sPartM[1][r * 64 + c]
                    + sPartM[2][r * 64 + c] + sPartM[3][r * 64 + c];
            atomicAdd(&g_WhOut[r * 64 + c], s);
        }
    }
}

// ---------------- k_final: output GAT layer + elu(V*out), 64 blocks ---------
__global__ void __launch_bounds__(256) k_final(const float* __restrict__ V,
                                               const float* __restrict__ aout,
                                               float* __restrict__ outp) {
    __shared__ float sAo[128];
    __shared__ float e1o[MAXR], e2o[MAXR];
    __shared__ float sAlpha[MAXE];
    __shared__ int   sJr[MAXE];
    __shared__ int   sRowOf[NN];
    __shared__ int sNe, sNr, sNc, sEi[MAXE], sEj[MAXE], sEr[MAXE], sEc[MAXE];
    __shared__ int sRows[MAXR], sCols[MAXR];
    int t = threadIdx.x, b = blockIdx.x;
    if (t < 32) warp_prep(t, &sNe, &sNr, &sNc, sEi, sEj, sEr, sEc, sRows, sCols);
    if (t < 128) sAo[t] = aout[t];
    for (int e = t; e < NN; e += 256) sRowOf[e] = -1;
    __syncthreads();
    int nrows = sNr, ne = sNe;
    if (t < nrows) sRowOf[sRows[t]] = t;
    int wid = t >> 5, lane = t & 31;
#pragma unroll
    for (int rr = 0; rr < 2; rr++) {
        int r = wid + 8 * rr;
        if (r < nrows) {
            float w0 = g_WhOut[r * NC + lane];
            float w1 = g_WhOut[r * NC + 32 + lane];
            float s1 = w0 * sAo[lane]      + w1 * sAo[32 + lane];
            float s2 = w0 * sAo[64 + lane] + w1 * sAo[96 + lane];
            for (int o = 16; o; o >>= 1) {
                s1 += __shfl_xor_sync(~0u, s1, o);
                s2 += __shfl_xor_sync(~0u, s2, o);
            }
            if (lane == 0) { e1o[r] = s1; e2o[r] = s2; }
        }
    }
    __syncthreads();
    if (t == 0) {
        float mm2[MAXR], d2[MAXR];
        float e2m = 0.f;   // inactive rows contribute e2 == 0 exactly
        for (int r = 0; r < nrows; r++) e2m = fmaxf(e2m, e2o[r]);
        for (int r = 0; r < nrows; r++) {
            float mm = lrelu(e1o[r] + e2m);
            float D = (float)(NN - nrows) * __expf(lrelu(e1o[r]) - mm);
            for (int q = 0; q < nrows; q++) D += __expf(lrelu(e1o[r] + e2o[q]) - mm);
            mm2[r] = mm; d2[r] = 1.f / D;
        }
        for (int ed = 0; ed < ne; ed++) {
            int r = sEr[ed];
            int jr = sRowOf[sEj[ed]];
            sJr[ed] = jr;
            sAlpha[ed] = (jr >= 0)
                ? __expf(lrelu(e1o[r] + e2o[jr]) - mm2[r]) * d2[r]
                : 0.f;
        }
    }
    __syncthreads();
    if (outp) {
        int base = b * (NN * NC / 64);          // 512 outputs per block
        for (int q = t; q < NN * NC / 64; q += 256) {
            int idx = base + q;
            int i = idx >> 6, k = idx & 63;
            int r = sRowOf[i];
            float val = 0.f;
            if (r >= 0) {
                float o2 = 0.f;
                for (int ed = 0; ed < ne; ed++)
                    if (sEr[ed] == r && sJr[ed] >= 0)
                        o2 += sAlpha[ed] * g_WhOut[sJr[ed] * NC + k];
                val = elu1(V[idx] * elu1(o2));
            }
            outp[idx] = val;
        }
    }
}

// ---------------- host ------------------------------------------------------
extern "C" void kernel_launch(void* const* d_in, const int* in_sizes, int n_in,
                              void* d_out, int out_size) {
    const float* X    = (const float*)d_in[0];
    const float* Wst  = (const float*)d_in[1];
    const float* ast  = (const float*)d_in[2];
    const float* Wout = (const float*)d_in[3];
    const float* aout = (const float*)d_in[4];
    const float* V    = (const float*)d_in[5];
    float* outbuf = (float*)d_out;

    float* adj_dst  = nullptr;
    float* feat_dst = nullptr;
    if (out_size >= NN * NN + NN * NC) { adj_dst = outbuf; feat_dst = outbuf + NN * NN; }
    else if (out_size == NN * NN)      { adj_dst = outbuf; }
    else                               { feat_dst = outbuf; }

    k_vvt   <<<dim3(16, 16), 256>>>(V);
    k_adj   <<<256, 256>>>(adj_dst);
    k_head  <<<512, 256>>>(X, Wst, ast);
    k_e2    <<<dim3(16, 16), 128>>>(X);
    k_epi   <<<512, 256>>>(X, Wout);
    k_final <<<64, 256>>>(V, aout, feat_dst);
}